// round 7
// baseline (speedup 1.0000x reference)
#include <cuda_runtime.h>
#include <cuda_bf16.h>
#include <cstdint>

// Problem dims
#define HN 32
#define HC 64
#define HH 96
#define HWD 96
#define HWW 9216        // 96*96
#define K7 448          // C*7

// Scratch (device globals; no allocations allowed)
__device__ float g_t2[HN * HC * HC];        // (n, c, d) channel attention (f32, atomics)
__device__ float g_t6[HN * HWW];            // (n, h*w)
__device__ float g_t9[HN * HC];             // (n, c)
__device__ uint32_t g_t8s[HN * HC * K7];    // (n, c, k) packed bf16 hi|lo<<16, incl 1/sqrt(448)
__device__ uint32_t g_xs[HN * HC * HWW];    // x packed bf16 hi|lo<<16

// ---- bf16 helpers ----
__device__ __forceinline__ uint32_t bfpair(float e0, float e1) {
    // low16 = bf16(e0), high16 = bf16(e1)
    uint32_t r;
    asm("cvt.rn.bf16x2.f32 %0, %1, %2;" : "=r"(r) : "f"(e1), "f"(e0));
    return r;
}
__device__ __forceinline__ float bfround(float v) {
    return __bfloat162float(__float2bfloat16_rn(v));
}
__device__ __forceinline__ uint32_t prmt(uint32_t a, uint32_t b, uint32_t sel) {
    uint32_t r;
    asm("prmt.b32 %0, %1, %2, %3;" : "=r"(r) : "r"(a), "r"(b), "r"(sel));
    return r;
}
__device__ __forceinline__ uint32_t packsplit(float v) {
    // bf16(v) | bf16(v - bf16(v)) << 16
    return bfpair(v, v - bfround(v));
}

// ---- warp mma: D(16x8,f32) += A(16x16,bf16) * B(16x8,bf16) ----
__device__ __forceinline__ void mma16816(float* d, const uint32_t* a,
                                         uint32_t b0, uint32_t b1) {
    asm volatile(
        "mma.sync.aligned.m16n8k16.row.col.f32.bf16.bf16.f32 "
        "{%0,%1,%2,%3}, {%4,%5,%6,%7}, {%8,%9}, {%0,%1,%2,%3};"
        : "+f"(d[0]), "+f"(d[1]), "+f"(d[2]), "+f"(d[3])
        : "r"(a[0]), "r"(a[1]), "r"(a[2]), "r"(a[3]), "r"(b0), "r"(b1));
}

// ---------------------------------------------------------------------------
__global__ void k_init() {
    int t = blockIdx.x * 256 + threadIdx.x;
    if (t < HN * HC * HC) g_t2[t] = 0.f;
    if (t < HN * HC)      g_t9[t] = 0.f;
}

// ---------------------------------------------------------------------------
// k_xsplit: pack x into bf16 hi/lo words. 18.87M elements, 4 per thread.
// ---------------------------------------------------------------------------
__global__ void __launch_bounds__(256) k_xsplit(const float* __restrict__ x) {
    size_t i = ((size_t)blockIdx.x * 256 + threadIdx.x) * 4;
    float4 v = *(const float4*)(x + i);
    uint4 o;
    o.x = packsplit(v.x);
    o.y = packsplit(v.y);
    o.z = packsplit(v.z);
    o.w = packsplit(v.w);
    *(uint4*)(g_xs + i) = o;
}

// ---------------------------------------------------------------------------
// k_t2_mma: t2[n,c,d] = sum_s x[n,c,s]*x_roll[n,d,s] / 96 via mma.sync bf16
// (3-product compensation). grid (8, n): 1152 s per block, 18 chunks of 64.
// smem tiles 64 rows x 32 words, stride 36 (conflict-free fragments).
// ---------------------------------------------------------------------------
#define T2B_S 1152
__global__ void __launch_bounds__(256) k_t2_mma(const float* __restrict__ x) {
    const int n = blockIdx.y;
    const int sc0 = blockIdx.x * T2B_S;
    __shared__ uint32_t Ah[64 * 36], Al[64 * 36];
    __shared__ uint32_t Bh[64 * 36], Bl[64 * 36];
    const int t = threadIdx.x;
    const int wid = t >> 5, lane = t & 31;
    const int warp_m = wid & 3, warp_n = wid >> 2;
    const int lr = lane >> 2, lp = lane & 3;

    float dacc[4][4];
#pragma unroll
    for (int i = 0; i < 4; i++)
#pragma unroll
        for (int q = 0; q < 4; q++) dacc[i][q] = 0.f;

    const float* xn = x + (size_t)n * HC * HWW;

    for (int ch = 0; ch < 18; ch++) {
        const int sbase = sc0 + ch * 64;
        __syncthreads();
#pragma unroll
        for (int rep = 0; rep < 8; rep++) {
            int i = t + rep * 256;
            int c = i >> 5, p = i & 31;
            int s = sbase + 2 * p;
            float2 va = *(const float2*)&xn[c * HWW + s];
            float ha0 = bfround(va.x), ha1 = bfround(va.y);
            Ah[c * 36 + p] = bfpair(ha0, ha1);
            Al[c * 36 + p] = bfpair(va.x - ha0, va.y - ha1);
            // rolled operand: src(h,w) = ((h+95)%96)*96 + (w+1)%96
            int h = s / 96, w = s - h * 96;      // w even, <= 94
            int hb = ((h + 95) % 96) * 96;
            float b0 = xn[c * HWW + hb + w + 1];
            float b1 = xn[c * HWW + hb + (w == 94 ? 0 : w + 2)];
            float hb0 = bfround(b0), hb1 = bfround(b1);
            Bh[c * 36 + p] = bfpair(hb0, hb1);
            Bl[c * 36 + p] = bfpair(b0 - hb0, b1 - hb1);
        }
        __syncthreads();

#pragma unroll
        for (int kg = 0; kg < 4; kg++) {
            uint32_t ah[4], al[4];
            int r0 = (warp_m * 16 + lr) * 36 + kg * 8;
            int r1 = r0 + 8 * 36;
            ah[0] = Ah[r0 + lp];     ah[1] = Ah[r1 + lp];
            ah[2] = Ah[r0 + 4 + lp]; ah[3] = Ah[r1 + 4 + lp];
            al[0] = Al[r0 + lp];     al[1] = Al[r1 + lp];
            al[2] = Al[r0 + 4 + lp]; al[3] = Al[r1 + 4 + lp];
#pragma unroll
            for (int nt = 0; nt < 4; nt++) {
                int nb = (warp_n * 32 + nt * 8 + lr) * 36 + kg * 8;
                uint32_t bh0 = Bh[nb + lp], bh1 = Bh[nb + 4 + lp];
                uint32_t bl0 = Bl[nb + lp], bl1 = Bl[nb + 4 + lp];
                mma16816(dacc[nt], ah, bh0, bh1);
                mma16816(dacc[nt], ah, bl0, bl1);
                mma16816(dacc[nt], al, bh0, bh1);
            }
        }
    }

    const float inv = 1.0f / 96.0f;
    float* t2p = g_t2 + n * HC * HC;
    const int c_a = warp_m * 16 + lr;
    const int c_b = c_a + 8;
#pragma unroll
    for (int nt = 0; nt < 4; nt++) {
        int dcol = warp_n * 32 + nt * 8 + lp * 2;
        atomicAdd(&t2p[c_a * HC + dcol],     dacc[nt][0] * inv);
        atomicAdd(&t2p[c_a * HC + dcol + 1], dacc[nt][1] * inv);
        atomicAdd(&t2p[c_b * HC + dcol],     dacc[nt][2] * inv);
        atomicAdd(&t2p[c_b * HC + dcol + 1], dacc[nt][3] * inv);
    }
}

// ---------------------------------------------------------------------------
// t6 (unchanged)
// ---------------------------------------------------------------------------
__global__ void __launch_bounds__(256) k_t6(const float* __restrict__ x,
                                            const float* __restrict__ w4,
                                            const float* __restrict__ p6) {
    const int n = blockIdx.y;
    const int h0 = blockIdx.x * 8;
    __shared__ float tile[12][104];
    __shared__ float coef[9];
    const int t = threadIdx.x;
    float acc[3];
#pragma unroll
    for (int k = 0; k < 3; k++) acc[k] = 0.f;
    const float* xn = x + (size_t)n * HC * HWW;

    for (int c = 0; c < HC; c++) {
        if (t < 9) coef[t] = w4[c * 9 + t] * p6[c];
        for (int idx = t; idx < 12 * 104; idx += 256) {
            int r = idx / 104, cw = idx - r * 104;
            float v = 0.f;
            if (cw < 100) {
                int y = h0 - 2 + r;
                int xc = cw - 2;
                if (y >= 0 && y < 96 && xc >= 0 && xc < 96)
                    v = xn[c * HWW + ((y + 95) % 96) * 96 + (xc + 1) % 96];
            }
            tile[r][cw] = v;
        }
        __syncthreads();
#pragma unroll
        for (int k = 0; k < 3; k++) {
            int o = t + k * 256;
            int r = o / 96, w = o - r * 96;
            float s = 0.f;
#pragma unroll
            for (int u = 0; u < 3; u++)
#pragma unroll
                for (int v = 0; v < 3; v++)
                    s += coef[u * 3 + v] * tile[r + 2 * u][w + 2 * v];
            acc[k] += s;
        }
        __syncthreads();
    }
    float* t6n = g_t6 + n * HWW;
#pragma unroll
    for (int k = 0; k < 3; k++) {
        int o = t + k * 256;
        t6n[(h0 + o / 96) * 96 + (o % 96)] = acc[k];
    }
}

// ---------------------------------------------------------------------------
// t9 (unchanged)
// ---------------------------------------------------------------------------
__global__ void __launch_bounds__(256) k_t9(const float* __restrict__ x,
                                            const float* __restrict__ w3) {
    const int n = blockIdx.z;
    const int c = blockIdx.y;
    const int h0 = blockIdx.x * 32;
    __shared__ float tile[36][104];
    __shared__ float w3s[25];
    __shared__ float red[8];
    const int t = threadIdx.x;
    const float* xc = x + ((size_t)n * HC + c) * HWW;

    if (t < 25) w3s[t] = w3[c * 25 + t];
    for (int idx = t; idx < 36 * 104; idx += 256) {
        int r = idx / 104, cw = idx - r * 104;
        float v = 0.f;
        if (cw < 100) {
            int y = h0 - 2 + r;
            int xcc = cw - 2;
            if (y >= 0 && y < 96 && xcc >= 0 && xcc < 96)
                v = xc[((y + 95) % 96) * 96 + (xcc + 1) % 96];
        }
        tile[r][cw] = v;
    }
    __syncthreads();

    const float* t6n = g_t6 + n * HWW;
    float local = 0.f;
#pragma unroll
    for (int pass = 0; pass < 3; pass++) {
        int q = t + pass * 256;
        int w = q % 96;
        int r0 = (q / 96) * 4;
        float a0 = 0.f, a1 = 0.f, a2 = 0.f, a3 = 0.f;
#pragma unroll
        for (int u = 0; u < 8; u++) {
            float v0 = tile[r0 + u][w + 0];
            float v1 = tile[r0 + u][w + 1];
            float v2 = tile[r0 + u][w + 2];
            float v3 = tile[r0 + u][w + 3];
            float v4 = tile[r0 + u][w + 4];
            if (u <= 4) {
                const float* wr = &w3s[u * 5];
                a0 += wr[0]*v0 + wr[1]*v1 + wr[2]*v2 + wr[3]*v3 + wr[4]*v4;
            }
            if (u >= 1 && u <= 5) {
                const float* wr = &w3s[(u - 1) * 5];
                a1 += wr[0]*v0 + wr[1]*v1 + wr[2]*v2 + wr[3]*v3 + wr[4]*v4;
            }
            if (u >= 2 && u <= 6) {
                const float* wr = &w3s[(u - 2) * 5];
                a2 += wr[0]*v0 + wr[1]*v1 + wr[2]*v2 + wr[3]*v3 + wr[4]*v4;
            }
            if (u >= 3) {
                const float* wr = &w3s[(u - 3) * 5];
                a3 += wr[0]*v0 + wr[1]*v1 + wr[2]*v2 + wr[3]*v3 + wr[4]*v4;
            }
        }
        const float* t6q = t6n + (h0 + r0) * 96 + w;
        local += a0 * t6q[0] + a1 * t6q[96] + a2 * t6q[192] + a3 * t6q[288];
    }
#pragma unroll
    for (int off = 16; off; off >>= 1) local += __shfl_down_sync(0xffffffffu, local, off);
    if ((t & 31) == 0) red[t >> 5] = local;
    __syncthreads();
    if (t < 8) {
        local = red[t];
#pragma unroll
        for (int off = 4; off; off >>= 1) local += __shfl_down_sync(0xffu, local, off);
        if (t == 0) atomicAdd(&g_t9[n * HC + c], local * (1.0f / 96.0f));
    }
}

// ---------------------------------------------------------------------------
// t8: writes PACKED bf16 hi/lo layout g_t8s[n][c][k] (k contiguous).
// ---------------------------------------------------------------------------
__global__ void __launch_bounds__(256) k_t8(const float* __restrict__ p5,
                                            const float* __restrict__ p8) {
    const int n = blockIdx.y;
    const int d0 = blockIdx.x * 32;
    __shared__ float t5s[64 * 64];
    __shared__ float p8s[64 * 32];
    const int t = threadIdx.x;
    const float* t2n = g_t2 + n * HC * HC;
    for (int idx = t; idx < 4096; idx += 256) t5s[idx] = p5[idx] * t2n[idx];
    for (int idx = t; idx < 2048; idx += 256) {
        int b = idx >> 5, dd = idx & 31;
        p8s[idx] = p8[b * K7 + d0 + dd];
    }
    __syncthreads();
    const float sc = 0.047245559126f;   // 1/sqrt(448)
#pragma unroll
    for (int k = 0; k < 8; k++) {
        int o = t + k * 256;
        int dl = o >> 6, c = o & 63;
        float s = 0.f;
#pragma unroll 8
        for (int b = 0; b < 64; b++) s += t5s[b * 64 + c] * p8s[b * 32 + dl];
        g_t8s[((size_t)(n * HC + c)) * K7 + d0 + dl] = packsplit(s * sc);
    }
}

// ---------------------------------------------------------------------------
// k_out: warp mma.sync bf16 implicit GEMM, 3-product compensated.
// D[c=64, s=128] per block, K=448 = 14 chunks of 32 (2 mma k-groups each).
// Tiles built from pre-packed g_t8s / g_xs with PRMT only (no float math).
// smem rows stride 18 words -> conflict-free fragment LDS.
// ---------------------------------------------------------------------------
__global__ void __launch_bounds__(256) k_out_mma(float* __restrict__ out) {
    const int n = blockIdx.y;
    const int s0 = blockIdx.x * 128;
    __shared__ uint32_t A_hi[64 * 18], A_lo[64 * 18];
    __shared__ uint32_t B_hi[128 * 18], B_lo[128 * 18];
    __shared__ float t9s[64];
    const int t = threadIdx.x;
    const int wid = t >> 5, lane = t & 31;
    const int warp_m = wid & 3, warp_n = wid >> 2;
    const int lr = lane >> 2, lp = lane & 3;

    if (t < 64) t9s[t] = g_t9[n * HC + t];

    float d[8][4];
#pragma unroll
    for (int i = 0; i < 8; i++)
#pragma unroll
        for (int q = 0; q < 4; q++) d[i][q] = 0.f;

    const uint32_t* xsn = g_xs + (size_t)n * HC * HWW;
    const uint32_t* t8n = g_t8s + (size_t)n * HC * K7;

    for (int ks = 0; ks < 14; ks++) {
        const int k0 = ks * 32;
        __syncthreads();
        // ---- A build: 64 c x 16 words ----
#pragma unroll
        for (int rep = 0; rep < 4; rep++) {
            int i = t + rep * 256;
            int c = i >> 4, p = i & 15;
            uint2 w2 = *(const uint2*)(t8n + c * K7 + k0 + 2 * p);
            A_hi[c * 18 + p] = prmt(w2.x, w2.y, 0x5410);
            A_lo[c * 18 + p] = prmt(w2.x, w2.y, 0x7632);
        }
        // ---- B build: 128 s x 16 words, unfold gather ----
#pragma unroll
        for (int rep = 0; rep < 8; rep++) {
            int i = t + rep * 256;
            int sl = i >> 4, p = i & 15;
            int s = s0 + sl;
            int h = s / 96, w = s - h * 96;
            int k = k0 + 2 * p;
            int cp = k / 7, j = k - cp * 7;
            int cp1 = cp, j1 = j + 1;
            if (j == 6) { cp1 = cp + 1; j1 = 0; }
            int wq0 = w + 2 * j - 6;
            int wq1 = w + 2 * j1 - 6;
            uint32_t e0 = (wq0 >= 0 && wq0 < 96) ? xsn[cp * HWW + h * 96 + wq0] : 0u;
            uint32_t e1 = (wq1 >= 0 && wq1 < 96) ? xsn[cp1 * HWW + h * 96 + wq1] : 0u;
            B_hi[sl * 18 + p] = prmt(e0, e1, 0x5410);
            B_lo[sl * 18 + p] = prmt(e0, e1, 0x7632);
        }
        __syncthreads();

#pragma unroll
        for (int kg = 0; kg < 2; kg++) {
            uint32_t ah[4], al[4];
            int r0 = (warp_m * 16 + lr) * 18 + kg * 8;
            int r1 = r0 + 8 * 18;
            ah[0] = A_hi[r0 + lp];     ah[1] = A_hi[r1 + lp];
            ah[2] = A_hi[r0 + 4 + lp]; ah[3] = A_hi[r1 + 4 + lp];
            al[0] = A_lo[r0 + lp];     al[1] = A_lo[r1 + lp];
            al[2] = A_lo[r0 + 4 + lp]; al[3] = A_lo[r1 + 4 + lp];
#pragma unroll
            for (int nt = 0; nt < 8; nt++) {
                int nb = (warp_n * 64 + nt * 8 + lr) * 18 + kg * 8;
                uint32_t bh0 = B_hi[nb + lp], bh1 = B_hi[nb + 4 + lp];
                uint32_t bl0 = B_lo[nb + lp], bl1 = B_lo[nb + 4 + lp];
                mma16816(d[nt], ah, bh0, bh1);
                mma16816(d[nt], ah, bl0, bl1);
                mma16816(d[nt], al, bh0, bh1);
            }
        }
    }

    // ---- epilogue: add t9, store float2 (s, s+1) ----
    const int c_a = warp_m * 16 + lr;
    const int c_b = c_a + 8;
    const float ta = t9s[c_a], tb = t9s[c_b];
#pragma unroll
    for (int nt = 0; nt < 8; nt++) {
        int sb = s0 + warp_n * 64 + nt * 8 + lp * 2;
        float2 o0 = make_float2(d[nt][0] + ta, d[nt][1] + ta);
        float2 o1 = make_float2(d[nt][2] + tb, d[nt][3] + tb);
        *(float2*)&out[((size_t)(n * HC + c_a)) * HWW + sb] = o0;
        *(float2*)&out[((size_t)(n * HC + c_b)) * HWW + sb] = o1;
    }
}

// ---------------------------------------------------------------------------
extern "C" void kernel_launch(void* const* d_in, const int* in_sizes, int n_in,
                              void* d_out, int out_size) {
    const float* x  = (const float*)d_in[0];
    const float* w3 = (const float*)d_in[1];
    const float* w4 = (const float*)d_in[2];
    const float* p5 = (const float*)d_in[3];
    const float* p6 = (const float*)d_in[4];
    const float* p8 = (const float*)d_in[5];
    float* out = (float*)d_out;

    k_init<<<512, 256>>>();
    k_xsplit<<<HN * HC * HWW / 1024, 256>>>(x);
    k_t2_mma<<<dim3(8, HN), 256>>>(x);
    k_t6<<<dim3(12, HN), 256>>>(x, w4, p6);
    k_t9<<<dim3(3, HC, HN), 256>>>(x, w3);
    k_t8<<<dim3(14, HN), 256>>>(p5, p8);
    k_out_mma<<<dim3(72, HN), 256>>>(out);
}

// round 8
// speedup vs baseline: 1.2394x; 1.2394x over previous
#include <cuda_runtime.h>
#include <cuda_bf16.h>
#include <cstdint>

// Problem dims
#define HN 32
#define HC 64
#define HH 96
#define HWD 96
#define HWW 9216        // 96*96
#define K7 448          // C*7

// Scratch (device globals; no allocations allowed)
__device__ float g_t2[HN * HC * HC];     // (n, c, d) channel attention
__device__ float g_t6[HN * HWW];         // (n, h*w)  (atomic accum)
__device__ float g_t9[HN * HC];          // (n, c)
__device__ float g_t8[HN * HC * K7];     // (n, c, k) TRANSPOSED, incl 1/sqrt(448)

// ---- packed f32x2 helpers (used by k_t2) ----
__device__ __forceinline__ unsigned long long ffma2(unsigned long long a,
                                                    unsigned long long b,
                                                    unsigned long long c) {
    unsigned long long d;
    asm("fma.rn.f32x2 %0, %1, %2, %3;" : "=l"(d) : "l"(a), "l"(b), "l"(c));
    return d;
}
__device__ __forceinline__ unsigned long long fpack2(float lo, float hi) {
    unsigned long long r;
    asm("mov.b64 %0, {%1, %2};" : "=l"(r) : "f"(lo), "f"(hi));
    return r;
}
__device__ __forceinline__ void funpack2(unsigned long long v, float& lo, float& hi) {
    asm("mov.b64 {%0, %1}, %2;" : "=f"(lo), "=f"(hi) : "l"(v));
}

// ---- bf16 helpers ----
__device__ __forceinline__ uint32_t bfpair(float e0, float e1) {
    // packs {low16 = bf16(e0), high16 = bf16(e1)}
    uint32_t r;
    asm("cvt.rn.bf16x2.f32 %0, %1, %2;" : "=r"(r) : "f"(e1), "f"(e0));
    return r;
}
__device__ __forceinline__ float bfround(float v) {
    return __bfloat162float(__float2bfloat16_rn(v));
}

// ---- warp mma: D(16x8,f32) += A(16x16,bf16) * B(16x8,bf16) ----
__device__ __forceinline__ void mma16816(float* d, const uint32_t* a,
                                         uint32_t b0, uint32_t b1) {
    asm volatile(
        "mma.sync.aligned.m16n8k16.row.col.f32.bf16.bf16.f32 "
        "{%0,%1,%2,%3}, {%4,%5,%6,%7}, {%8,%9}, {%0,%1,%2,%3};"
        : "+f"(d[0]), "+f"(d[1]), "+f"(d[2]), "+f"(d[3])
        : "r"(a[0]), "r"(a[1]), "r"(a[2]), "r"(a[3]), "r"(b0), "r"(b1));
}

// ---------------------------------------------------------------------------
__global__ void k_init() {
    int t = blockIdx.x * 256 + threadIdx.x;
    if (t < HN * HC * HC) g_t2[t] = 0.f;
    if (t < HN * HC)      g_t9[t] = 0.f;
    if (t < HN * HWW)     g_t6[t] = 0.f;
}

// ---------------------------------------------------------------------------
// t2[n,c,d] = sum_s x[n,c,s] * x_roll[n,d,s] / 96   (R6 scalar version)
// ---------------------------------------------------------------------------
#define T2_NCH 36
#define T2_CS  256

__global__ void __launch_bounds__(64) k_t2(const float* __restrict__ x) {
    const int n = blockIdx.y;
    const int sbase0 = blockIdx.x * T2_CS;
    __shared__ __align__(16) float As[64][66];
    __shared__ __align__(16) float Bs[64][66];
    const int t = threadIdx.x;
    const int tx = t & 7, ty = t >> 3;
    const int c0 = ty * 8, d0 = tx * 8;

    unsigned long long acc[4][8];
#pragma unroll
    for (int u = 0; u < 4; u++)
#pragma unroll
        for (int v = 0; v < 8; v++) acc[u][v] = 0ULL;

    const float* xn = x + (size_t)n * HC * HWW;

    for (int st = 0; st < T2_CS; st += 64) {
        const int sbase = sbase0 + st;
#pragma unroll 4
        for (int it = 0; it < 64; it++) {
            As[t][it] = xn[it * HWW + sbase + t];
            int s = sbase + t;
            int h = s / 96, w = s - h * 96;
            int src = ((h + 95) % 96) * 96 + (w + 1) % 96;
            Bs[t][it] = xn[it * HWW + src];
        }
        __syncthreads();
#pragma unroll 8
        for (int ks = 0; ks < 64; ks++) {
            unsigned long long a2[4];
#pragma unroll
            for (int u = 0; u < 4; u++)
                a2[u] = *(const unsigned long long*)&As[ks][c0 + 2 * u];
#pragma unroll
            for (int v = 0; v < 8; v++) {
                float b = Bs[ks][d0 + v];
                unsigned long long b2 = fpack2(b, b);
#pragma unroll
                for (int u = 0; u < 4; u++) acc[u][v] = ffma2(a2[u], b2, acc[u][v]);
            }
        }
        __syncthreads();
    }

    const float inv = 1.0f / 96.0f;
    float* t2p = g_t2 + n * HC * HC;
#pragma unroll
    for (int u = 0; u < 4; u++)
#pragma unroll
        for (int v = 0; v < 8; v++) {
            float lo, hi;
            funpack2(acc[u][v], lo, hi);
            atomicAdd(&t2p[(c0 + 2 * u) * HC + d0 + v], lo * inv);
            atomicAdd(&t2p[(c0 + 2 * u + 1) * HC + d0 + v], hi * inv);
        }
}

// ---------------------------------------------------------------------------
// t6[n,h,w] = sum_c p6[c] * dwconv3x3_dil2(t1)[n,c,h,w]
// NEW: channel loop split across blocks. grid (12 hchunks, 8 cchunks, n).
// Each block: 8 rows x 96 cols, 8 channels, register accum, atomicAdd out.
// ---------------------------------------------------------------------------
__global__ void __launch_bounds__(256) k_t6(const float* __restrict__ x,
                                            const float* __restrict__ w4,
                                            const float* __restrict__ p6) {
    const int n = blockIdx.z;
    const int c0 = blockIdx.y * 8;
    const int h0 = blockIdx.x * 8;
    __shared__ float tile[12][104];
    __shared__ float coef[9];
    const int t = threadIdx.x;
    float acc[3];
#pragma unroll
    for (int k = 0; k < 3; k++) acc[k] = 0.f;
    const float* xn = x + (size_t)n * HC * HWW;

    for (int ci = 0; ci < 8; ci++) {
        const int c = c0 + ci;
        if (t < 9) coef[t] = w4[c * 9 + t] * p6[c];
        for (int idx = t; idx < 12 * 104; idx += 256) {
            int r = idx / 104, cw = idx - r * 104;
            float v = 0.f;
            if (cw < 100) {
                int y = h0 - 2 + r;
                int xc = cw - 2;
                if (y >= 0 && y < 96 && xc >= 0 && xc < 96)
                    v = xn[c * HWW + ((y + 95) % 96) * 96 + (xc + 1) % 96];
            }
            tile[r][cw] = v;
        }
        __syncthreads();
#pragma unroll
        for (int k = 0; k < 3; k++) {
            int o = t + k * 256;
            int r = o / 96, w = o - r * 96;
            float s = 0.f;
#pragma unroll
            for (int u = 0; u < 3; u++)
#pragma unroll
                for (int v = 0; v < 3; v++)
                    s += coef[u * 3 + v] * tile[r + 2 * u][w + 2 * v];
            acc[k] += s;
        }
        __syncthreads();
    }
    float* t6n = g_t6 + n * HWW;
#pragma unroll
    for (int k = 0; k < 3; k++) {
        int o = t + k * 256;
        atomicAdd(&t6n[(h0 + o / 96) * 96 + (o % 96)], acc[k]);
    }
}

// ---------------------------------------------------------------------------
// t9 (unchanged)
// ---------------------------------------------------------------------------
__global__ void __launch_bounds__(256) k_t9(const float* __restrict__ x,
                                            const float* __restrict__ w3) {
    const int n = blockIdx.z;
    const int c = blockIdx.y;
    const int h0 = blockIdx.x * 32;
    __shared__ float tile[36][104];
    __shared__ float w3s[25];
    __shared__ float red[8];
    const int t = threadIdx.x;
    const float* xc = x + ((size_t)n * HC + c) * HWW;

    if (t < 25) w3s[t] = w3[c * 25 + t];
    for (int idx = t; idx < 36 * 104; idx += 256) {
        int r = idx / 104, cw = idx - r * 104;
        float v = 0.f;
        if (cw < 100) {
            int y = h0 - 2 + r;
            int xcc = cw - 2;
            if (y >= 0 && y < 96 && xcc >= 0 && xcc < 96)
                v = xc[((y + 95) % 96) * 96 + (xcc + 1) % 96];
        }
        tile[r][cw] = v;
    }
    __syncthreads();

    const float* t6n = g_t6 + n * HWW;
    float local = 0.f;
#pragma unroll
    for (int pass = 0; pass < 3; pass++) {
        int q = t + pass * 256;
        int w = q % 96;
        int r0 = (q / 96) * 4;
        float a0 = 0.f, a1 = 0.f, a2 = 0.f, a3 = 0.f;
#pragma unroll
        for (int u = 0; u < 8; u++) {
            float v0 = tile[r0 + u][w + 0];
            float v1 = tile[r0 + u][w + 1];
            float v2 = tile[r0 + u][w + 2];
            float v3 = tile[r0 + u][w + 3];
            float v4 = tile[r0 + u][w + 4];
            if (u <= 4) {
                const float* wr = &w3s[u * 5];
                a0 += wr[0]*v0 + wr[1]*v1 + wr[2]*v2 + wr[3]*v3 + wr[4]*v4;
            }
            if (u >= 1 && u <= 5) {
                const float* wr = &w3s[(u - 1) * 5];
                a1 += wr[0]*v0 + wr[1]*v1 + wr[2]*v2 + wr[3]*v3 + wr[4]*v4;
            }
            if (u >= 2 && u <= 6) {
                const float* wr = &w3s[(u - 2) * 5];
                a2 += wr[0]*v0 + wr[1]*v1 + wr[2]*v2 + wr[3]*v3 + wr[4]*v4;
            }
            if (u >= 3) {
                const float* wr = &w3s[(u - 3) * 5];
                a3 += wr[0]*v0 + wr[1]*v1 + wr[2]*v2 + wr[3]*v3 + wr[4]*v4;
            }
        }
        const float* t6q = t6n + (h0 + r0) * 96 + w;
        local += a0 * t6q[0] + a1 * t6q[96] + a2 * t6q[192] + a3 * t6q[288];
    }
#pragma unroll
    for (int off = 16; off; off >>= 1) local += __shfl_down_sync(0xffffffffu, local, off);
    if ((t & 31) == 0) red[t >> 5] = local;
    __syncthreads();
    if (t < 8) {
        local = red[t];
#pragma unroll
        for (int off = 4; off; off >>= 1) local += __shfl_down_sync(0xffu, local, off);
        if (t == 0) atomicAdd(&g_t9[n * HC + c], local * (1.0f / 96.0f));
    }
}

// ---------------------------------------------------------------------------
// t8: writes TRANSPOSED layout g_t8[n][c][k] (k contiguous).
// ---------------------------------------------------------------------------
__global__ void __launch_bounds__(256) k_t8(const float* __restrict__ p5,
                                            const float* __restrict__ p8) {
    const int n = blockIdx.y;
    const int d0 = blockIdx.x * 32;
    __shared__ float t5s[64 * 64];
    __shared__ float p8s[64 * 32];
    const int t = threadIdx.x;
    const float* t2n = g_t2 + n * HC * HC;
    for (int idx = t; idx < 4096; idx += 256) t5s[idx] = p5[idx] * t2n[idx];
    for (int idx = t; idx < 2048; idx += 256) {
        int b = idx >> 5, dd = idx & 31;
        p8s[idx] = p8[b * K7 + d0 + dd];
    }
    __syncthreads();
    const float sc = 0.047245559126f;   // 1/sqrt(448)
#pragma unroll
    for (int k = 0; k < 8; k++) {
        int o = t + k * 256;
        int dl = o >> 6, c = o & 63;
        float s = 0.f;
#pragma unroll 8
        for (int b = 0; b < 64; b++) s += t5s[b * 64 + c] * p8s[b * 32 + dl];
        g_t8[((size_t)(n * HC + c)) * K7 + d0 + dl] = s * sc;
    }
}

// ---------------------------------------------------------------------------
// k_out: warp-level mma.sync bf16 implicit GEMM (R6 version, unchanged).
// ---------------------------------------------------------------------------
__global__ void __launch_bounds__(256) k_out_mma(const float* __restrict__ x,
                                                 float* __restrict__ out) {
    const int n = blockIdx.y;
    const int s0 = blockIdx.x * 128;
    __shared__ uint32_t A_hi[64 * 9], A_lo[64 * 9];
    __shared__ uint32_t B_hi[128 * 9], B_lo[128 * 9];
    __shared__ float t9s[64];
    const int t = threadIdx.x;
    const int wid = t >> 5, lane = t & 31;
    const int warp_m = wid & 3, warp_n = wid >> 2;
    const int lr = lane >> 2;     // 0..7
    const int lp = lane & 3;      // pair index 0..3

    if (t < 64) t9s[t] = g_t9[n * HC + t];

    float d[8][4];
#pragma unroll
    for (int i = 0; i < 8; i++)
#pragma unroll
        for (int q = 0; q < 4; q++) d[i][q] = 0.f;

    const float* xn = x + (size_t)n * HC * HWW;
    const float* t8n = g_t8 + (size_t)n * HC * K7;

    for (int ks = 0; ks < 28; ks++) {
        const int k0 = ks * 16;
        __syncthreads();
#pragma unroll
        for (int rep = 0; rep < 2; rep++) {
            int i = t + rep * 256;
            int c = i >> 3, p = i & 7;
            float2 v = *(const float2*)&t8n[c * K7 + k0 + 2 * p];
            float h0 = bfround(v.x), h1 = bfround(v.y);
            A_hi[c * 9 + p] = bfpair(h0, h1);
            A_lo[c * 9 + p] = bfpair(v.x - h0, v.y - h1);
        }
#pragma unroll
        for (int rep = 0; rep < 4; rep++) {
            int i = t + rep * 256;
            int sl = i >> 3, p = i & 7;
            int s = s0 + sl;
            int h = s / 96, w = s - h * 96;
            int k = k0 + 2 * p;
            int cp = k / 7, j = k - cp * 7;
            int cp1 = cp, j1 = j + 1;
            if (j == 6) { cp1 = cp + 1; j1 = 0; }
            int wq0 = w + 2 * j - 6;
            int wq1 = w + 2 * j1 - 6;
            float v0 = (wq0 >= 0 && wq0 < 96) ? xn[cp * HWW + h * 96 + wq0] : 0.f;
            float v1 = (wq1 >= 0 && wq1 < 96) ? xn[cp1 * HWW + h * 96 + wq1] : 0.f;
            float h0 = bfround(v0), h1 = bfround(v1);
            B_hi[sl * 9 + p] = bfpair(h0, h1);
            B_lo[sl * 9 + p] = bfpair(v0 - h0, v1 - h1);
        }
        __syncthreads();

        uint32_t ah[4], al[4];
        {
            int r0 = (warp_m * 16 + lr) * 9;
            int r1 = (warp_m * 16 + 8 + lr) * 9;
            ah[0] = A_hi[r0 + lp];     ah[1] = A_hi[r1 + lp];
            ah[2] = A_hi[r0 + 4 + lp]; ah[3] = A_hi[r1 + 4 + lp];
            al[0] = A_lo[r0 + lp];     al[1] = A_lo[r1 + lp];
            al[2] = A_lo[r0 + 4 + lp]; al[3] = A_lo[r1 + 4 + lp];
        }
#pragma unroll
        for (int nt = 0; nt < 8; nt++) {
            int nb = (warp_n * 64 + nt * 8 + lr) * 9;
            uint32_t bh0 = B_hi[nb + lp], bh1 = B_hi[nb + 4 + lp];
            uint32_t bl0 = B_lo[nb + lp], bl1 = B_lo[nb + 4 + lp];
            mma16816(d[nt], ah, bh0, bh1);
            mma16816(d[nt], ah, bl0, bl1);
            mma16816(d[nt], al, bh0, bh1);
        }
    }

    const int c_a = warp_m * 16 + lr;
    const int c_b = c_a + 8;
    const float ta = t9s[c_a], tb = t9s[c_b];
#pragma unroll
    for (int nt = 0; nt < 8; nt++) {
        int sb = s0 + warp_n * 64 + nt * 8 + lp * 2;
        float2 o0 = make_float2(d[nt][0] + ta, d[nt][1] + ta);
        float2 o1 = make_float2(d[nt][2] + tb, d[nt][3] + tb);
        *(float2*)&out[((size_t)(n * HC + c_a)) * HWW + sb] = o0;
        *(float2*)&out[((size_t)(n * HC + c_b)) * HWW + sb] = o1;
    }
}

// ---------------------------------------------------------------------------
extern "C" void kernel_launch(void* const* d_in, const int* in_sizes, int n_in,
                              void* d_out, int out_size) {
    const float* x  = (const float*)d_in[0];
    const float* w3 = (const float*)d_in[1];
    const float* w4 = (const float*)d_in[2];
    const float* p5 = (const float*)d_in[3];
    const float* p6 = (const float*)d_in[4];
    const float* p8 = (const float*)d_in[5];
    float* out = (float*)d_out;

    k_init<<<1152, 256>>>();
    k_t2<<<dim3(T2_NCH, HN), 64>>>(x);
    k_t6<<<dim3(12, 8, HN), 256>>>(x, w4, p6);
    k_t9<<<dim3(3, HC, HN), 256>>>(x, w3);
    k_t8<<<dim3(14, HN), 256>>>(p5, p8);
    k_out_mma<<<dim3(72, HN), 256>>>(x, out);
}

// round 9
// speedup vs baseline: 1.3322x; 1.0749x over previous
#include <cuda_runtime.h>
#include <cuda_bf16.h>
#include <cstdint>

// Problem dims
#define HN 32
#define HC 64
#define HH 96
#define HWD 96
#define HWW 9216        // 96*96
#define K7 448          // C*7

// Scratch (device globals; no allocations allowed)
__device__ float g_t2[HN * HC * HC];     // (n, c, d) channel attention
__device__ float g_t6[HN * HWW];         // (n, h*w)  (atomic accum)
__device__ float g_t9[HN * HC];          // (n, c)
__device__ float g_t8[HN * HC * K7];     // (n, c, k) TRANSPOSED, incl 1/sqrt(448)

// ---- packed f32x2 helpers (used by k_t2) ----
__device__ __forceinline__ unsigned long long ffma2(unsigned long long a,
                                                    unsigned long long b,
                                                    unsigned long long c) {
    unsigned long long d;
    asm("fma.rn.f32x2 %0, %1, %2, %3;" : "=l"(d) : "l"(a), "l"(b), "l"(c));
    return d;
}
__device__ __forceinline__ unsigned long long fpack2(float lo, float hi) {
    unsigned long long r;
    asm("mov.b64 %0, {%1, %2};" : "=l"(r) : "f"(lo), "f"(hi));
    return r;
}
__device__ __forceinline__ void funpack2(unsigned long long v, float& lo, float& hi) {
    asm("mov.b64 {%0, %1}, %2;" : "=f"(lo), "=f"(hi) : "l"(v));
}

// ---- bf16 helpers ----
__device__ __forceinline__ uint32_t bfpair(float e0, float e1) {
    // packs {low16 = bf16(e0), high16 = bf16(e1)}
    uint32_t r;
    asm("cvt.rn.bf16x2.f32 %0, %1, %2;" : "=r"(r) : "f"(e1), "f"(e0));
    return r;
}
__device__ __forceinline__ float bfround(float v) {
    return __bfloat162float(__float2bfloat16_rn(v));
}
__device__ __forceinline__ uint32_t smem_u32(const void* p) {
    uint32_t a;
    asm("{ .reg .u64 t; cvta.to.shared.u64 t, %1; cvt.u32.u64 %0, t; }" : "=r"(a) : "l"(p));
    return a;
}

// ---- warp mma: D(16x8,f32) += A(16x16,bf16) * B(16x8,bf16) ----
__device__ __forceinline__ void mma16816(float* d, const uint32_t* a,
                                         uint32_t b0, uint32_t b1) {
    asm volatile(
        "mma.sync.aligned.m16n8k16.row.col.f32.bf16.bf16.f32 "
        "{%0,%1,%2,%3}, {%4,%5,%6,%7}, {%8,%9}, {%0,%1,%2,%3};"
        : "+f"(d[0]), "+f"(d[1]), "+f"(d[2]), "+f"(d[3])
        : "r"(a[0]), "r"(a[1]), "r"(a[2]), "r"(a[3]), "r"(b0), "r"(b1));
}
__device__ __forceinline__ void ldsm_x4(uint32_t& r0, uint32_t& r1,
                                        uint32_t& r2, uint32_t& r3, uint32_t a) {
    asm volatile("ldmatrix.sync.aligned.m8n8.x4.shared.b16 {%0,%1,%2,%3}, [%4];"
                 : "=r"(r0), "=r"(r1), "=r"(r2), "=r"(r3) : "r"(a));
}
__device__ __forceinline__ void ldsm_x2(uint32_t& r0, uint32_t& r1, uint32_t a) {
    asm volatile("ldmatrix.sync.aligned.m8n8.x2.shared.b16 {%0,%1}, [%2];"
                 : "=r"(r0), "=r"(r1) : "r"(a));
}

// ---------------------------------------------------------------------------
__global__ void k_init() {
    int t = blockIdx.x * 256 + threadIdx.x;
    if (t < HN * HC * HC) g_t2[t] = 0.f;
    if (t < HN * HC)      g_t9[t] = 0.f;
    if (t < HN * HWW)     g_t6[t] = 0.f;
}

// ---------------------------------------------------------------------------
// t2 (unchanged from R8)
// ---------------------------------------------------------------------------
#define T2_NCH 36
#define T2_CS  256

__global__ void __launch_bounds__(64) k_t2(const float* __restrict__ x) {
    const int n = blockIdx.y;
    const int sbase0 = blockIdx.x * T2_CS;
    __shared__ __align__(16) float As[64][66];
    __shared__ __align__(16) float Bs[64][66];
    const int t = threadIdx.x;
    const int tx = t & 7, ty = t >> 3;
    const int c0 = ty * 8, d0 = tx * 8;

    unsigned long long acc[4][8];
#pragma unroll
    for (int u = 0; u < 4; u++)
#pragma unroll
        for (int v = 0; v < 8; v++) acc[u][v] = 0ULL;

    const float* xn = x + (size_t)n * HC * HWW;

    for (int st = 0; st < T2_CS; st += 64) {
        const int sbase = sbase0 + st;
#pragma unroll 4
        for (int it = 0; it < 64; it++) {
            As[t][it] = xn[it * HWW + sbase + t];
            int s = sbase + t;
            int h = s / 96, w = s - h * 96;
            int src = ((h + 95) % 96) * 96 + (w + 1) % 96;
            Bs[t][it] = xn[it * HWW + src];
        }
        __syncthreads();
#pragma unroll 8
        for (int ks = 0; ks < 64; ks++) {
            unsigned long long a2[4];
#pragma unroll
            for (int u = 0; u < 4; u++)
                a2[u] = *(const unsigned long long*)&As[ks][c0 + 2 * u];
#pragma unroll
            for (int v = 0; v < 8; v++) {
                float b = Bs[ks][d0 + v];
                unsigned long long b2 = fpack2(b, b);
#pragma unroll
                for (int u = 0; u < 4; u++) acc[u][v] = ffma2(a2[u], b2, acc[u][v]);
            }
        }
        __syncthreads();
    }

    const float inv = 1.0f / 96.0f;
    float* t2p = g_t2 + n * HC * HC;
#pragma unroll
    for (int u = 0; u < 4; u++)
#pragma unroll
        for (int v = 0; v < 8; v++) {
            float lo, hi;
            funpack2(acc[u][v], lo, hi);
            atomicAdd(&t2p[(c0 + 2 * u) * HC + d0 + v], lo * inv);
            atomicAdd(&t2p[(c0 + 2 * u + 1) * HC + d0 + v], hi * inv);
        }
}

// ---------------------------------------------------------------------------
// t6 (unchanged from R8: channel-split + atomics)
// ---------------------------------------------------------------------------
__global__ void __launch_bounds__(256) k_t6(const float* __restrict__ x,
                                            const float* __restrict__ w4,
                                            const float* __restrict__ p6) {
    const int n = blockIdx.z;
    const int c0 = blockIdx.y * 8;
    const int h0 = blockIdx.x * 8;
    __shared__ float tile[12][104];
    __shared__ float coef[9];
    const int t = threadIdx.x;
    float acc[3];
#pragma unroll
    for (int k = 0; k < 3; k++) acc[k] = 0.f;
    const float* xn = x + (size_t)n * HC * HWW;

    for (int ci = 0; ci < 8; ci++) {
        const int c = c0 + ci;
        if (t < 9) coef[t] = w4[c * 9 + t] * p6[c];
        for (int idx = t; idx < 12 * 104; idx += 256) {
            int r = idx / 104, cw = idx - r * 104;
            float v = 0.f;
            if (cw < 100) {
                int y = h0 - 2 + r;
                int xc = cw - 2;
                if (y >= 0 && y < 96 && xc >= 0 && xc < 96)
                    v = xn[c * HWW + ((y + 95) % 96) * 96 + (xc + 1) % 96];
            }
            tile[r][cw] = v;
        }
        __syncthreads();
#pragma unroll
        for (int k = 0; k < 3; k++) {
            int o = t + k * 256;
            int r = o / 96, w = o - r * 96;
            float s = 0.f;
#pragma unroll
            for (int u = 0; u < 3; u++)
#pragma unroll
                for (int v = 0; v < 3; v++)
                    s += coef[u * 3 + v] * tile[r + 2 * u][w + 2 * v];
            acc[k] += s;
        }
        __syncthreads();
    }
    float* t6n = g_t6 + n * HWW;
#pragma unroll
    for (int k = 0; k < 3; k++) {
        int o = t + k * 256;
        atomicAdd(&t6n[(h0 + o / 96) * 96 + (o % 96)], acc[k]);
    }
}

// ---------------------------------------------------------------------------
// t9 (unchanged)
// ---------------------------------------------------------------------------
__global__ void __launch_bounds__(256) k_t9(const float* __restrict__ x,
                                            const float* __restrict__ w3) {
    const int n = blockIdx.z;
    const int c = blockIdx.y;
    const int h0 = blockIdx.x * 32;
    __shared__ float tile[36][104];
    __shared__ float w3s[25];
    __shared__ float red[8];
    const int t = threadIdx.x;
    const float* xc = x + ((size_t)n * HC + c) * HWW;

    if (t < 25) w3s[t] = w3[c * 25 + t];
    for (int idx = t; idx < 36 * 104; idx += 256) {
        int r = idx / 104, cw = idx - r * 104;
        float v = 0.f;
        if (cw < 100) {
            int y = h0 - 2 + r;
            int xcc = cw - 2;
            if (y >= 0 && y < 96 && xcc >= 0 && xcc < 96)
                v = xc[((y + 95) % 96) * 96 + (xcc + 1) % 96];
        }
        tile[r][cw] = v;
    }
    __syncthreads();

    const float* t6n = g_t6 + n * HWW;
    float local = 0.f;
#pragma unroll
    for (int pass = 0; pass < 3; pass++) {
        int q = t + pass * 256;
        int w = q % 96;
        int r0 = (q / 96) * 4;
        float a0 = 0.f, a1 = 0.f, a2 = 0.f, a3 = 0.f;
#pragma unroll
        for (int u = 0; u < 8; u++) {
            float v0 = tile[r0 + u][w + 0];
            float v1 = tile[r0 + u][w + 1];
            float v2 = tile[r0 + u][w + 2];
            float v3 = tile[r0 + u][w + 3];
            float v4 = tile[r0 + u][w + 4];
            if (u <= 4) {
                const float* wr = &w3s[u * 5];
                a0 += wr[0]*v0 + wr[1]*v1 + wr[2]*v2 + wr[3]*v3 + wr[4]*v4;
            }
            if (u >= 1 && u <= 5) {
                const float* wr = &w3s[(u - 1) * 5];
                a1 += wr[0]*v0 + wr[1]*v1 + wr[2]*v2 + wr[3]*v3 + wr[4]*v4;
            }
            if (u >= 2 && u <= 6) {
                const float* wr = &w3s[(u - 2) * 5];
                a2 += wr[0]*v0 + wr[1]*v1 + wr[2]*v2 + wr[3]*v3 + wr[4]*v4;
            }
            if (u >= 3) {
                const float* wr = &w3s[(u - 3) * 5];
                a3 += wr[0]*v0 + wr[1]*v1 + wr[2]*v2 + wr[3]*v3 + wr[4]*v4;
            }
        }
        const float* t6q = t6n + (h0 + r0) * 96 + w;
        local += a0 * t6q[0] + a1 * t6q[96] + a2 * t6q[192] + a3 * t6q[288];
    }
#pragma unroll
    for (int off = 16; off; off >>= 1) local += __shfl_down_sync(0xffffffffu, local, off);
    if ((t & 31) == 0) red[t >> 5] = local;
    __syncthreads();
    if (t < 8) {
        local = red[t];
#pragma unroll
        for (int off = 4; off; off >>= 1) local += __shfl_down_sync(0xffu, local, off);
        if (t == 0) atomicAdd(&g_t9[n * HC + c], local * (1.0f / 96.0f));
    }
}

// ---------------------------------------------------------------------------
// t8 (unchanged)
// ---------------------------------------------------------------------------
__global__ void __launch_bounds__(256) k_t8(const float* __restrict__ p5,
                                            const float* __restrict__ p8) {
    const int n = blockIdx.y;
    const int d0 = blockIdx.x * 32;
    __shared__ float t5s[64 * 64];
    __shared__ float p8s[64 * 32];
    const int t = threadIdx.x;
    const float* t2n = g_t2 + n * HC * HC;
    for (int idx = t; idx < 4096; idx += 256) t5s[idx] = p5[idx] * t2n[idx];
    for (int idx = t; idx < 2048; idx += 256) {
        int b = idx >> 5, dd = idx & 31;
        p8s[idx] = p8[b * K7 + d0 + dd];
    }
    __syncthreads();
    const float sc = 0.047245559126f;   // 1/sqrt(448)
#pragma unroll
    for (int k = 0; k < 8; k++) {
        int o = t + k * 256;
        int dl = o >> 6, c = o & 63;
        float s = 0.f;
#pragma unroll 8
        for (int b = 0; b < 64; b++) s += t5s[b * 64 + c] * p8s[b * 32 + dl];
        g_t8[((size_t)(n * HC + c)) * K7 + d0 + dl] = s * sc;
    }
}

// ---------------------------------------------------------------------------
// k_out v3: mma.sync bf16 implicit GEMM, 3-product compensated.
// K-chunk 32, 14 chunks. x rows cached in smem (removes gather LDG
// amplification), xc/A double-buffered software pipeline, ldmatrix fragments.
// smem word layout (dynamic):
//   A_hi: buf*1280         (64 rows x stride 20)
//   A_lo: 2560 + buf*1280
//   B_hi: 5120             (128 rows x stride 20, single buffer)
//   B_lo: 7680
//   xc:   10240 + buf*1368 (6 ch x stride 228; rows stride 114; w' in [0,112))
//   t9s:  12976
// ---------------------------------------------------------------------------
#define KO_AHI(buf) ((buf) * 1280)
#define KO_ALO(buf) (2560 + (buf) * 1280)
#define KO_BHI 5120
#define KO_BLO 7680
#define KO_XC(buf) (10240 + (buf) * 1368)
#define KO_T9 12976
#define KO_WORDS 13040

__global__ void __launch_bounds__(256) k_out_mma(const float* __restrict__ x,
                                                 float* __restrict__ out) {
    extern __shared__ __align__(16) float smf[];
    uint32_t* smw = (uint32_t*)smf;
    const uint32_t sbase = smem_u32(smf);
    const int n = blockIdx.y;
    const int s0 = blockIdx.x * 128;
    const int h0 = s0 / 96;
    const int t = threadIdx.x;
    const int wid = t >> 5, lane = t & 31;
    const int warp_m = wid & 3, warp_n = wid >> 2;
    const int lr = lane >> 2, lp = lane & 3;

    const float* xn = x + (size_t)n * HC * HWW;
    const float* t8n = g_t8 + (size_t)n * HC * K7;

    // ---- per-thread chunk-invariant precompute ----
    const int p_b = t & 15;          // B/A word index (0..15)
    const int slb = t >> 4;          // B row base; A row base
    // B-build per-rep constants: sl = slb + 16*rep
    int wb[8];
#pragma unroll
    for (int rep = 0; rep < 8; rep++) {
        int sl = slb + 16 * rep;
        int s = s0 + sl;
        int h = s / 96;
        wb[rep] = (h - h0) * 114 + (s - h * 96);
    }
    // xc-load per-rep constants (6 reps over 1344 logical elems)
    int xci[6], xsts[6], xgofs[6];
    bool xval[6];
#pragma unroll
    for (int rep = 0; rep < 6; rep++) {
        int idx = t + rep * 256;
        bool inb = idx < 1344;
        int ci = idx / 224;
        int rem = idx - ci * 224;
        int hrx = rem / 112;
        int wq = rem - hrx * 112 - 6;
        xci[rep] = inb ? ci : 0;
        xsts[rep] = inb ? (ci * 228 + hrx * 114 + wq + 6) : 0;
        xval[rep] = inb && (wq >= 0) && (wq < 96);
        xgofs[rep] = (h0 + hrx) * 96 + (wq < 0 ? 0 : (wq > 95 ? 95 : wq));
        if (!inb) xval[rep] = false;
        if (!inb) xsts[rep] = KO_XC(0) - KO_XC(0); // 0; written guarded below
    }
    // ldmatrix lane addresses
    const int g8 = lane >> 3, fr = lane & 7;
    const int aw = (warp_m * 16 + ((g8 & 1) << 3) + fr) * 20 + ((g8 >> 1) << 2);
    const int bw = (warp_n * 64 + fr) * 20 + ((g8 & 1) << 2);

    float d[8][4];
#pragma unroll
    for (int i = 0; i < 8; i++)
#pragma unroll
        for (int q = 0; q < 4; q++) d[i][q] = 0.f;

    // ---- prefetch helper (macro-ish lambda): load xc[buf], A[buf] for chunk ch ----
    auto prefetch = [&](int ch, int buf) {
        const int k0 = ch * 32;
        const int cp_lo = k0 / 7;
        // xc
        float* xcb = smf + KO_XC(buf);
#pragma unroll
        for (int rep = 0; rep < 6; rep++) {
            int idx = t + rep * 256;
            if (idx < 1344) {
                int cp = cp_lo + xci[rep];
                float v = (xval[rep] && cp < 64) ? xn[cp * HWW + xgofs[rep]] : 0.f;
                xcb[xsts[rep]] = v;
            }
        }
        // A tiles
        uint32_t* ah = smw + KO_AHI(buf);
        uint32_t* al = smw + KO_ALO(buf);
#pragma unroll
        for (int rep = 0; rep < 4; rep++) {
            int c = slb + 16 * rep;
            float2 v = *(const float2*)&t8n[c * K7 + k0 + 2 * p_b];
            float h0v = bfround(v.x), h1v = bfround(v.y);
            int sts = c * 20 + p_b;
            ah[sts] = bfpair(h0v, h1v);
            al[sts] = bfpair(v.x - h0v, v.y - h1v);
        }
    };

    // ---- prologue ----
    if (t < 64) smf[KO_T9 + t] = g_t9[n * HC + t];
    prefetch(0, 0);
    __syncthreads();

    for (int ch = 0; ch < 14; ch++) {
        const int cur = ch & 1;
        const int k0 = ch * 32;
        const int cp_lo = k0 / 7;
        // ---- B build from xc[cur] ----
        {
            const float* xcf = smf + KO_XC(cur);
            int k = k0 + 2 * p_b;
            int cp0 = k / 7;
            int j0 = k - cp0 * 7;
            int cp1 = (j0 == 6) ? cp0 + 1 : cp0;
            int j1 = (j0 == 6) ? 0 : j0 + 1;
            int off0 = (cp0 - cp_lo) * 228 + 2 * j0;
            int off1 = (cp1 - cp_lo) * 228 + 2 * j1;
            uint32_t* bh = smw + KO_BHI;
            uint32_t* bl = smw + KO_BLO;
            int stsb = slb * 20 + p_b;
#pragma unroll
            for (int rep = 0; rep < 8; rep++) {
                float v0 = xcf[off0 + wb[rep]];
                float v1 = xcf[off1 + wb[rep]];
                float h0v = bfround(v0), h1v = bfround(v1);
                int sts = stsb + rep * 320;
                bh[sts] = bfpair(h0v, h1v);
                bl[sts] = bfpair(v0 - h0v, v1 - h1v);
            }
        }
        // ---- prefetch next chunk into other buffer ----
        if (ch < 13) prefetch(ch + 1, cur ^ 1);
        __syncthreads();

        // ---- mma ----
        uint32_t ah[2][4], al[2][4];
#pragma unroll
        for (int kg = 0; kg < 2; kg++) {
            ldsm_x4(ah[kg][0], ah[kg][1], ah[kg][2], ah[kg][3],
                    sbase + (uint32_t)(KO_AHI(cur) + aw + kg * 8) * 4u);
            ldsm_x4(al[kg][0], al[kg][1], al[kg][2], al[kg][3],
                    sbase + (uint32_t)(KO_ALO(cur) + aw + kg * 8) * 4u);
        }
#pragma unroll
        for (int nt = 0; nt < 8; nt++) {
#pragma unroll
            for (int kg = 0; kg < 2; kg++) {
                uint32_t bh0, bh1, bl0, bl1;
                uint32_t bword = (uint32_t)(bw + nt * 160 + kg * 8);
                ldsm_x2(bh0, bh1, sbase + (uint32_t)(KO_BHI + bword) * 4u);
                ldsm_x2(bl0, bl1, sbase + (uint32_t)(KO_BLO + bword) * 4u);
                mma16816(d[nt], ah[kg], bh0, bh1);
                mma16816(d[nt], ah[kg], bl0, bl1);
                mma16816(d[nt], al[kg], bh0, bh1);
            }
        }
        __syncthreads();
    }

    // ---- epilogue: add t9, store float2 ----
    const int c_a = warp_m * 16 + lr;
    const int c_b = c_a + 8;
    const float ta = smf[KO_T9 + c_a], tb = smf[KO_T9 + c_b];
#pragma unroll
    for (int nt = 0; nt < 8; nt++) {
        int sb = s0 + warp_n * 64 + nt * 8 + lp * 2;
        float2 o0 = make_float2(d[nt][0] + ta, d[nt][1] + ta);
        float2 o1 = make_float2(d[nt][2] + tb, d[nt][3] + tb);
        *(float2*)&out[((size_t)(n * HC + c_a)) * HWW + sb] = o0;
        *(float2*)&out[((size_t)(n * HC + c_b)) * HWW + sb] = o1;
    }
}

// ---------------------------------------------------------------------------
extern "C" void kernel_launch(void* const* d_in, const int* in_sizes, int n_in,
                              void* d_out, int out_size) {
    const float* x  = (const float*)d_in[0];
    const float* w3 = (const float*)d_in[1];
    const float* w4 = (const float*)d_in[2];
    const float* p5 = (const float*)d_in[3];
    const float* p6 = (const float*)d_in[4];
    const float* p8 = (const float*)d_in[5];
    float* out = (float*)d_out;

    cudaFuncSetAttribute(k_out_mma, cudaFuncAttributeMaxDynamicSharedMemorySize,
                         KO_WORDS * 4);

    k_init<<<1152, 256>>>();
    k_t2<<<dim3(T2_NCH, HN), 64>>>(x);
    k_t6<<<dim3(12, 8, HN), 256>>>(x, w4, p6);
    k_t9<<<dim3(3, HC, HN), 256>>>(x, w3);
    k_t8<<<dim3(14, HN), 256>>>(p5, p8);
    k_out_mma<<<dim3(72, HN), 256, KO_WORDS * 4>>>(x, out);
}

// round 10
// speedup vs baseline: 1.3635x; 1.0235x over previous
#include <cuda_runtime.h>
#include <cuda_bf16.h>
#include <cstdint>

// Problem dims
#define HN 32
#define HC 64
#define HH 96
#define HWD 96
#define HWW 9216        // 96*96
#define K7 448          // C*7

// Scratch (device globals; no allocations allowed)
__device__ float g_t2[HN * HC * HC];     // (n, c, d) channel attention
__device__ float g_t6[HN * HWW];         // (n, h*w)  (atomic accum)
__device__ float g_t9[HN * HC];          // (n, c)
__device__ float g_t8[HN * HC * K7];     // (n, c, k) TRANSPOSED, incl 1/sqrt(448)

// ---- bf16 helpers ----
__device__ __forceinline__ uint32_t bfpair(float e0, float e1) {
    // packs {low16 = bf16(e0), high16 = bf16(e1)}
    uint32_t r;
    asm("cvt.rn.bf16x2.f32 %0, %1, %2;" : "=r"(r) : "f"(e1), "f"(e0));
    return r;
}
__device__ __forceinline__ float bfround(float v) {
    return __bfloat162float(__float2bfloat16_rn(v));
}
__device__ __forceinline__ uint32_t smem_u32(const void* p) {
    uint32_t a;
    asm("{ .reg .u64 t; cvta.to.shared.u64 t, %1; cvt.u32.u64 %0, t; }" : "=r"(a) : "l"(p));
    return a;
}

// ---- warp mma: D(16x8,f32) += A(16x16,bf16) * B(16x8,bf16) ----
__device__ __forceinline__ void mma16816(float* d, const uint32_t* a,
                                         uint32_t b0, uint32_t b1) {
    asm volatile(
        "mma.sync.aligned.m16n8k16.row.col.f32.bf16.bf16.f32 "
        "{%0,%1,%2,%3}, {%4,%5,%6,%7}, {%8,%9}, {%0,%1,%2,%3};"
        : "+f"(d[0]), "+f"(d[1]), "+f"(d[2]), "+f"(d[3])
        : "r"(a[0]), "r"(a[1]), "r"(a[2]), "r"(a[3]), "r"(b0), "r"(b1));
}
__device__ __forceinline__ void ldsm_x4(uint32_t& r0, uint32_t& r1,
                                        uint32_t& r2, uint32_t& r3, uint32_t a) {
    asm volatile("ldmatrix.sync.aligned.m8n8.x4.shared.b16 {%0,%1,%2,%3}, [%4];"
                 : "=r"(r0), "=r"(r1), "=r"(r2), "=r"(r3) : "r"(a));
}
__device__ __forceinline__ void ldsm_x2(uint32_t& r0, uint32_t& r1, uint32_t a) {
    asm volatile("ldmatrix.sync.aligned.m8n8.x2.shared.b16 {%0,%1}, [%2];"
                 : "=r"(r0), "=r"(r1) : "r"(a));
}

// ---------------------------------------------------------------------------
__global__ void k_init() {
    int t = blockIdx.x * 256 + threadIdx.x;
    if (t < HN * HC * HC) g_t2[t] = 0.f;
    if (t < HN * HC)      g_t9[t] = 0.f;
    if (t < HN * HWW)     g_t6[t] = 0.f;
}

// ---------------------------------------------------------------------------
// k_t2_mma: t2[n,c,d] = sum_s x[n,c,s]*x_roll[n,d,s] / 96 via mma.sync bf16
// (3-product compensation, numerics validated in R7). grid (8, n):
// 1152 s per block, 18 chunks of 64. smem tiles 64 rows x 32 words,
// stride 36 (conflict-free fragments).
// ---------------------------------------------------------------------------
#define T2B_S 1152
__global__ void __launch_bounds__(256) k_t2_mma(const float* __restrict__ x) {
    const int n = blockIdx.y;
    const int sc0 = blockIdx.x * T2B_S;
    __shared__ uint32_t Ah[64 * 36], Al[64 * 36];
    __shared__ uint32_t Bh[64 * 36], Bl[64 * 36];
    const int t = threadIdx.x;
    const int wid = t >> 5, lane = t & 31;
    const int warp_m = wid & 3, warp_n = wid >> 2;
    const int lr = lane >> 2, lp = lane & 3;

    float dacc[4][4];
#pragma unroll
    for (int i = 0; i < 4; i++)
#pragma unroll
        for (int q = 0; q < 4; q++) dacc[i][q] = 0.f;

    const float* xn = x + (size_t)n * HC * HWW;

    for (int ch = 0; ch < 18; ch++) {
        const int sbase = sc0 + ch * 64;
        __syncthreads();
#pragma unroll
        for (int rep = 0; rep < 8; rep++) {
            int i = t + rep * 256;
            int c = i >> 5, p = i & 31;
            int s = sbase + 2 * p;
            float2 va = *(const float2*)&xn[c * HWW + s];
            float ha0 = bfround(va.x), ha1 = bfround(va.y);
            Ah[c * 36 + p] = bfpair(ha0, ha1);
            Al[c * 36 + p] = bfpair(va.x - ha0, va.y - ha1);
            // rolled operand: src(h,w) = ((h+95)%96)*96 + (w+1)%96
            int h = s / 96, w = s - h * 96;      // w even, <= 94
            int hb = ((h + 95) % 96) * 96;
            float b0 = xn[c * HWW + hb + w + 1];
            float b1 = xn[c * HWW + hb + (w == 94 ? 0 : w + 2)];
            float hb0 = bfround(b0), hb1 = bfround(b1);
            Bh[c * 36 + p] = bfpair(hb0, hb1);
            Bl[c * 36 + p] = bfpair(b0 - hb0, b1 - hb1);
        }
        __syncthreads();

#pragma unroll
        for (int kg = 0; kg < 4; kg++) {
            uint32_t ah[4], al[4];
            int r0 = (warp_m * 16 + lr) * 36 + kg * 8;
            int r1 = r0 + 8 * 36;
            ah[0] = Ah[r0 + lp];     ah[1] = Ah[r1 + lp];
            ah[2] = Ah[r0 + 4 + lp]; ah[3] = Ah[r1 + 4 + lp];
            al[0] = Al[r0 + lp];     al[1] = Al[r1 + lp];
            al[2] = Al[r0 + 4 + lp]; al[3] = Al[r1 + 4 + lp];
#pragma unroll
            for (int nt = 0; nt < 4; nt++) {
                int nb = (warp_n * 32 + nt * 8 + lr) * 36 + kg * 8;
                uint32_t bh0 = Bh[nb + lp], bh1 = Bh[nb + 4 + lp];
                uint32_t bl0 = Bl[nb + lp], bl1 = Bl[nb + 4 + lp];
                mma16816(dacc[nt], ah, bh0, bh1);
                mma16816(dacc[nt], ah, bl0, bl1);
                mma16816(dacc[nt], al, bh0, bh1);
            }
        }
    }

    const float inv = 1.0f / 96.0f;
    float* t2p = g_t2 + n * HC * HC;
    const int c_a = warp_m * 16 + lr;
    const int c_b = c_a + 8;
#pragma unroll
    for (int nt = 0; nt < 4; nt++) {
        int dcol = warp_n * 32 + nt * 8 + lp * 2;
        atomicAdd(&t2p[c_a * HC + dcol],     dacc[nt][0] * inv);
        atomicAdd(&t2p[c_a * HC + dcol + 1], dacc[nt][1] * inv);
        atomicAdd(&t2p[c_b * HC + dcol],     dacc[nt][2] * inv);
        atomicAdd(&t2p[c_b * HC + dcol + 1], dacc[nt][3] * inv);
    }
}

// ---------------------------------------------------------------------------
// t6 (unchanged from R8: channel-split + atomics)
// ---------------------------------------------------------------------------
__global__ void __launch_bounds__(256) k_t6(const float* __restrict__ x,
                                            const float* __restrict__ w4,
                                            const float* __restrict__ p6) {
    const int n = blockIdx.z;
    const int c0 = blockIdx.y * 8;
    const int h0 = blockIdx.x * 8;
    __shared__ float tile[12][104];
    __shared__ float coef[9];
    const int t = threadIdx.x;
    float acc[3];
#pragma unroll
    for (int k = 0; k < 3; k++) acc[k] = 0.f;
    const float* xn = x + (size_t)n * HC * HWW;

    for (int ci = 0; ci < 8; ci++) {
        const int c = c0 + ci;
        if (t < 9) coef[t] = w4[c * 9 + t] * p6[c];
        for (int idx = t; idx < 12 * 104; idx += 256) {
            int r = idx / 104, cw = idx - r * 104;
            float v = 0.f;
            if (cw < 100) {
                int y = h0 - 2 + r;
                int xc = cw - 2;
                if (y >= 0 && y < 96 && xc >= 0 && xc < 96)
                    v = xn[c * HWW + ((y + 95) % 96) * 96 + (xc + 1) % 96];
            }
            tile[r][cw] = v;
        }
        __syncthreads();
#pragma unroll
        for (int k = 0; k < 3; k++) {
            int o = t + k * 256;
            int r = o / 96, w = o - r * 96;
            float s = 0.f;
#pragma unroll
            for (int u = 0; u < 3; u++)
#pragma unroll
                for (int v = 0; v < 3; v++)
                    s += coef[u * 3 + v] * tile[r + 2 * u][w + 2 * v];
            acc[k] += s;
        }
        __syncthreads();
    }
    float* t6n = g_t6 + n * HWW;
#pragma unroll
    for (int k = 0; k < 3; k++) {
        int o = t + k * 256;
        atomicAdd(&t6n[(h0 + o / 96) * 96 + (o % 96)], acc[k]);
    }
}

// ---------------------------------------------------------------------------
// t9 (unchanged)
// ---------------------------------------------------------------------------
__global__ void __launch_bounds__(256) k_t9(const float* __restrict__ x,
                                            const float* __restrict__ w3) {
    const int n = blockIdx.z;
    const int c = blockIdx.y;
    const int h0 = blockIdx.x * 32;
    __shared__ float tile[36][104];
    __shared__ float w3s[25];
    __shared__ float red[8];
    const int t = threadIdx.x;
    const float* xc = x + ((size_t)n * HC + c) * HWW;

    if (t < 25) w3s[t] = w3[c * 25 + t];
    for (int idx = t; idx < 36 * 104; idx += 256) {
        int r = idx / 104, cw = idx - r * 104;
        float v = 0.f;
        if (cw < 100) {
            int y = h0 - 2 + r;
            int xcc = cw - 2;
            if (y >= 0 && y < 96 && xcc >= 0 && xcc < 96)
                v = xc[((y + 95) % 96) * 96 + (xcc + 1) % 96];
        }
        tile[r][cw] = v;
    }
    __syncthreads();

    const float* t6n = g_t6 + n * HWW;
    float local = 0.f;
#pragma unroll
    for (int pass = 0; pass < 3; pass++) {
        int q = t + pass * 256;
        int w = q % 96;
        int r0 = (q / 96) * 4;
        float a0 = 0.f, a1 = 0.f, a2 = 0.f, a3 = 0.f;
#pragma unroll
        for (int u = 0; u < 8; u++) {
            float v0 = tile[r0 + u][w + 0];
            float v1 = tile[r0 + u][w + 1];
            float v2 = tile[r0 + u][w + 2];
            float v3 = tile[r0 + u][w + 3];
            float v4 = tile[r0 + u][w + 4];
            if (u <= 4) {
                const float* wr = &w3s[u * 5];
                a0 += wr[0]*v0 + wr[1]*v1 + wr[2]*v2 + wr[3]*v3 + wr[4]*v4;
            }
            if (u >= 1 && u <= 5) {
                const float* wr = &w3s[(u - 1) * 5];
                a1 += wr[0]*v0 + wr[1]*v1 + wr[2]*v2 + wr[3]*v3 + wr[4]*v4;
            }
            if (u >= 2 && u <= 6) {
                const float* wr = &w3s[(u - 2) * 5];
                a2 += wr[0]*v0 + wr[1]*v1 + wr[2]*v2 + wr[3]*v3 + wr[4]*v4;
            }
            if (u >= 3) {
                const float* wr = &w3s[(u - 3) * 5];
                a3 += wr[0]*v0 + wr[1]*v1 + wr[2]*v2 + wr[3]*v3 + wr[4]*v4;
            }
        }
        const float* t6q = t6n + (h0 + r0) * 96 + w;
        local += a0 * t6q[0] + a1 * t6q[96] + a2 * t6q[192] + a3 * t6q[288];
    }
#pragma unroll
    for (int off = 16; off; off >>= 1) local += __shfl_down_sync(0xffffffffu, local, off);
    if ((t & 31) == 0) red[t >> 5] = local;
    __syncthreads();
    if (t < 8) {
        local = red[t];
#pragma unroll
        for (int off = 4; off; off >>= 1) local += __shfl_down_sync(0xffu, local, off);
        if (t == 0) atomicAdd(&g_t9[n * HC + c], local * (1.0f / 96.0f));
    }
}

// ---------------------------------------------------------------------------
// t8 (unchanged)
// ---------------------------------------------------------------------------
__global__ void __launch_bounds__(256) k_t8(const float* __restrict__ p5,
                                            const float* __restrict__ p8) {
    const int n = blockIdx.y;
    const int d0 = blockIdx.x * 32;
    __shared__ float t5s[64 * 64];
    __shared__ float p8s[64 * 32];
    const int t = threadIdx.x;
    const float* t2n = g_t2 + n * HC * HC;
    for (int idx = t; idx < 4096; idx += 256) t5s[idx] = p5[idx] * t2n[idx];
    for (int idx = t; idx < 2048; idx += 256) {
        int b = idx >> 5, dd = idx & 31;
        p8s[idx] = p8[b * K7 + d0 + dd];
    }
    __syncthreads();
    const float sc = 0.047245559126f;   // 1/sqrt(448)
#pragma unroll
    for (int k = 0; k < 8; k++) {
        int o = t + k * 256;
        int dl = o >> 6, c = o & 63;
        float s = 0.f;
#pragma unroll 8
        for (int b = 0; b < 64; b++) s += t5s[b * 64 + c] * p8s[b * 32 + dl];
        g_t8[((size_t)(n * HC + c)) * K7 + d0 + dl] = s * sc;
    }
}

// ---------------------------------------------------------------------------
// k_out v3 (unchanged from R9 — frozen this round for attribution)
// ---------------------------------------------------------------------------
#define KO_AHI(buf) ((buf) * 1280)
#define KO_ALO(buf) (2560 + (buf) * 1280)
#define KO_BHI 5120
#define KO_BLO 7680
#define KO_XC(buf) (10240 + (buf) * 1368)
#define KO_T9 12976
#define KO_WORDS 13040

__global__ void __launch_bounds__(256) k_out_mma(const float* __restrict__ x,
                                                 float* __restrict__ out) {
    extern __shared__ __align__(16) float smf[];
    uint32_t* smw = (uint32_t*)smf;
    const uint32_t sbase = smem_u32(smf);
    const int n = blockIdx.y;
    const int s0 = blockIdx.x * 128;
    const int h0 = s0 / 96;
    const int t = threadIdx.x;
    const int wid = t >> 5, lane = t & 31;
    const int warp_m = wid & 3, warp_n = wid >> 2;
    const int lr = lane >> 2, lp = lane & 3;

    const float* xn = x + (size_t)n * HC * HWW;
    const float* t8n = g_t8 + (size_t)n * HC * K7;

    const int p_b = t & 15;
    const int slb = t >> 4;
    int wb[8];
#pragma unroll
    for (int rep = 0; rep < 8; rep++) {
        int sl = slb + 16 * rep;
        int s = s0 + sl;
        int h = s / 96;
        wb[rep] = (h - h0) * 114 + (s - h * 96);
    }
    int xci[6], xsts[6], xgofs[6];
    bool xval[6];
#pragma unroll
    for (int rep = 0; rep < 6; rep++) {
        int idx = t + rep * 256;
        bool inb = idx < 1344;
        int ci = idx / 224;
        int rem = idx - ci * 224;
        int hrx = rem / 112;
        int wq = rem - hrx * 112 - 6;
        xci[rep] = inb ? ci : 0;
        xsts[rep] = inb ? (ci * 228 + hrx * 114 + wq + 6) : 0;
        xval[rep] = inb && (wq >= 0) && (wq < 96);
        xgofs[rep] = (h0 + hrx) * 96 + (wq < 0 ? 0 : (wq > 95 ? 95 : wq));
        if (!inb) xval[rep] = false;
    }
    const int g8 = lane >> 3, fr = lane & 7;
    const int aw = (warp_m * 16 + ((g8 & 1) << 3) + fr) * 20 + ((g8 >> 1) << 2);
    const int bw = (warp_n * 64 + fr) * 20 + ((g8 & 1) << 2);

    float d[8][4];
#pragma unroll
    for (int i = 0; i < 8; i++)
#pragma unroll
        for (int q = 0; q < 4; q++) d[i][q] = 0.f;

    auto prefetch = [&](int ch, int buf) {
        const int k0 = ch * 32;
        const int cp_lo = k0 / 7;
        float* xcb = smf + KO_XC(buf);
#pragma unroll
        for (int rep = 0; rep < 6; rep++) {
            int idx = t + rep * 256;
            if (idx < 1344) {
                int cp = cp_lo + xci[rep];
                float v = (xval[rep] && cp < 64) ? xn[cp * HWW + xgofs[rep]] : 0.f;
                xcb[xsts[rep]] = v;
            }
        }
        uint32_t* ah = smw + KO_AHI(buf);
        uint32_t* al = smw + KO_ALO(buf);
#pragma unroll
        for (int rep = 0; rep < 4; rep++) {
            int c = slb + 16 * rep;
            float2 v = *(const float2*)&t8n[c * K7 + k0 + 2 * p_b];
            float h0v = bfround(v.x), h1v = bfround(v.y);
            int sts = c * 20 + p_b;
            ah[sts] = bfpair(h0v, h1v);
            al[sts] = bfpair(v.x - h0v, v.y - h1v);
        }
    };

    if (t < 64) smf[KO_T9 + t] = g_t9[n * HC + t];
    prefetch(0, 0);
    __syncthreads();

    for (int ch = 0; ch < 14; ch++) {
        const int cur = ch & 1;
        const int k0 = ch * 32;
        const int cp_lo = k0 / 7;
        {
            const float* xcf = smf + KO_XC(cur);
            int k = k0 + 2 * p_b;
            int cp0 = k / 7;
            int j0 = k - cp0 * 7;
            int cp1 = (j0 == 6) ? cp0 + 1 : cp0;
            int j1 = (j0 == 6) ? 0 : j0 + 1;
            int off0 = (cp0 - cp_lo) * 228 + 2 * j0;
            int off1 = (cp1 - cp_lo) * 228 + 2 * j1;
            uint32_t* bh = smw + KO_BHI;
            uint32_t* bl = smw + KO_BLO;
            int stsb = slb * 20 + p_b;
#pragma unroll
            for (int rep = 0; rep < 8; rep++) {
                float v0 = xcf[off0 + wb[rep]];
                float v1 = xcf[off1 + wb[rep]];
                float h0v = bfround(v0), h1v = bfround(v1);
                int sts = stsb + rep * 320;
                bh[sts] = bfpair(h0v, h1v);
                bl[sts] = bfpair(v0 - h0v, v1 - h1v);
            }
        }
        if (ch < 13) prefetch(ch + 1, cur ^ 1);
        __syncthreads();

        uint32_t ah[2][4], al[2][4];
#pragma unroll
        for (int kg = 0; kg < 2; kg++) {
            ldsm_x4(ah[kg][0], ah[kg][1], ah[kg][2], ah[kg][3],
                    sbase + (uint32_t)(KO_AHI(cur) + aw + kg * 8) * 4u);
            ldsm_x4(al[kg][0], al[kg][1], al[kg][2], al[kg][3],
                    sbase + (uint32_t)(KO_ALO(cur) + aw + kg * 8) * 4u);
        }
#pragma unroll
        for (int nt = 0; nt < 8; nt++) {
#pragma unroll
            for (int kg = 0; kg < 2; kg++) {
                uint32_t bh0, bh1, bl0, bl1;
                uint32_t bword = (uint32_t)(bw + nt * 160 + kg * 8);
                ldsm_x2(bh0, bh1, sbase + (uint32_t)(KO_BHI + bword) * 4u);
                ldsm_x2(bl0, bl1, sbase + (uint32_t)(KO_BLO + bword) * 4u);
                mma16816(d[nt], ah[kg], bh0, bh1);
                mma16816(d[nt], ah[kg], bl0, bl1);
                mma16816(d[nt], al[kg], bh0, bh1);
            }
        }
        __syncthreads();
    }

    const int c_a = warp_m * 16 + lr;
    const int c_b = c_a + 8;
    const float ta = smf[KO_T9 + c_a], tb = smf[KO_T9 + c_b];
#pragma unroll
    for (int nt = 0; nt < 8; nt++) {
        int sb = s0 + warp_n * 64 + nt * 8 + lp * 2;
        float2 o0 = make_float2(d[nt][0] + ta, d[nt][1] + ta);
        float2 o1 = make_float2(d[nt][2] + tb, d[nt][3] + tb);
        *(float2*)&out[((size_t)(n * HC + c_a)) * HWW + sb] = o0;
        *(float2*)&out[((size_t)(n * HC + c_b)) * HWW + sb] = o1;
    }
}

// ---------------------------------------------------------------------------
extern "C" void kernel_launch(void* const* d_in, const int* in_sizes, int n_in,
                              void* d_out, int out_size) {
    const float* x  = (const float*)d_in[0];
    const float* w3 = (const float*)d_in[1];
    const float* w4 = (const float*)d_in[2];
    const float* p5 = (const float*)d_in[3];
    const float* p6 = (const float*)d_in[4];
    const float* p8 = (const float*)d_in[5];
    float* out = (float*)d_out;

    cudaFuncSetAttribute(k_out_mma, cudaFuncAttributeMaxDynamicSharedMemorySize,
                         KO_WORDS * 4);

    k_init<<<1152, 256>>>();
    k_t2_mma<<<dim3(8, HN), 256>>>(x);
    k_t6<<<dim3(12, 8, HN), 256>>>(x, w4, p6);
    k_t9<<<dim3(3, HC, HN), 256>>>(x, w3);
    k_t8<<<dim3(14, HN), 256>>>(p5, p8);
    k_out_mma<<<dim3(72, HN), 256, KO_WORDS * 4>>>(x, out);
}